// round 1
// baseline (speedup 1.0000x reference)
#include <cuda_runtime.h>
#include <math.h>

#define B_   16
#define T_   243
#define J_   17
#define D_   257
#define E_   256
#define W_   3
#define KW_  7
#define ROWS (B_ * J_ * T_)   // 66096

// Scratch (no allocation allowed in kernel_launch)
__device__ float g_spatial[(size_t)ROWS * E_];
__device__ float g_q[(size_t)ROWS * E_];
__device__ float g_k[(size_t)ROWS * E_];
__device__ float g_v[(size_t)ROWS * E_];

// ---------------------------------------------------------------------------
// Kernel 1: Lorentz log-map at origin (spatial part), with layout transpose
//   input  x_seq [B, T, J, 257]
//   output g_spatial [(b*J+j)*T + t, 256]
// ---------------------------------------------------------------------------
__global__ void logmap_kernel(const float* __restrict__ x)
{
    int row = blockIdx.x;          // row = bj*T + t
    int bj  = row / T_;
    int t   = row - bj * T_;
    int b   = bj / J_;
    int j   = bj - b * J_;
    size_t base = ((size_t)(b * T_ + t) * J_ + j) * D_;

    int d = threadIdx.x;           // 0..255
    float s = x[base + 1 + d];

    // block reduce sum of s^2
    float v = s * s;
    #pragma unroll
    for (int o = 16; o > 0; o >>= 1) v += __shfl_xor_sync(0xffffffffu, v, o);
    __shared__ float ws[8];
    int lane = d & 31, wid = d >> 5;
    if (lane == 0) ws[wid] = v;
    __syncthreads();

    __shared__ float scale_sh;
    if (d == 0) {
        float tot = 0.f;
        #pragma unroll
        for (int i = 0; i < 8; i++) tot += ws[i];
        float xn = fmaxf(sqrtf(tot), 1e-7f);
        float xt = x[base];
        float a  = acoshf(fmaxf(xt, 1.0f + 1e-7f));
        scale_sh = a / xn;
    }
    __syncthreads();

    g_spatial[(size_t)row * E_ + d] = scale_sh * s;
}

// ---------------------------------------------------------------------------
// Kernel 2: fused QKV SGEMM.  out[m, n] = sum_k spatial[m,k] * W[n,k] + bias[n]
// N dimension fused: cols [0,256)->Q, [256,512)->K, [512,768)->V.
// BM=128, BN=128, BK=8, 256 threads, 8x8 microtile.
// ---------------------------------------------------------------------------
#define BM 128
#define BN 128
#define BK 8

__global__ __launch_bounds__(256) void qkv_gemm(
    const float* __restrict__ Wq, const float* __restrict__ bq,
    const float* __restrict__ Wk, const float* __restrict__ bk,
    const float* __restrict__ Wv, const float* __restrict__ bv)
{
    __shared__ float As[BK][BM];
    __shared__ float Bs[BK][BN];

    int bm0 = blockIdx.x * BM;
    int bn0 = blockIdx.y * BN;           // 0,128,...,640
    int which = bn0 >> 8;                // 0=q,1=k,2=v (BN=128 divides 256)
    int ncol0 = bn0 & 255;

    const float* Wm   = (which == 0) ? Wq : (which == 1) ? Wk : Wv;
    const float* bias = (which == 0) ? bq : (which == 1) ? bk : bv;
    float*       outp = (which == 0) ? g_q : (which == 1) ? g_k : g_v;

    int tid = threadIdx.x;

    // global load indices: each thread loads one float4 of A and one of B per step
    int arow = bm0 + (tid >> 1);
    int acol = (tid & 1) * 4;
    int brow = ncol0 + (tid >> 1);       // always < 256
    int bcol = (tid & 1) * 4;
    int srow = tid >> 1;                 // 0..127

    float acc[8][8];
    #pragma unroll
    for (int i = 0; i < 8; i++)
        #pragma unroll
        for (int jj = 0; jj < 8; jj++) acc[i][jj] = 0.f;

    int tm0 = (tid >> 4) * 8;
    int tn0 = (tid & 15) * 8;

    for (int k0 = 0; k0 < E_; k0 += BK) {
        float4 av = make_float4(0.f, 0.f, 0.f, 0.f);
        if (arow < ROWS)
            av = *reinterpret_cast<const float4*>(&g_spatial[(size_t)arow * E_ + k0 + acol]);
        float4 bv4 = *reinterpret_cast<const float4*>(&Wm[(size_t)brow * E_ + k0 + bcol]);

        As[acol + 0][srow] = av.x;
        As[acol + 1][srow] = av.y;
        As[acol + 2][srow] = av.z;
        As[acol + 3][srow] = av.w;
        Bs[bcol + 0][srow] = bv4.x;
        Bs[bcol + 1][srow] = bv4.y;
        Bs[bcol + 2][srow] = bv4.z;
        Bs[bcol + 3][srow] = bv4.w;
        __syncthreads();

        #pragma unroll
        for (int kk = 0; kk < BK; kk++) {
            float ar[8], br[8];
            *reinterpret_cast<float4*>(&ar[0]) = *reinterpret_cast<const float4*>(&As[kk][tm0]);
            *reinterpret_cast<float4*>(&ar[4]) = *reinterpret_cast<const float4*>(&As[kk][tm0 + 4]);
            *reinterpret_cast<float4*>(&br[0]) = *reinterpret_cast<const float4*>(&Bs[kk][tn0]);
            *reinterpret_cast<float4*>(&br[4]) = *reinterpret_cast<const float4*>(&Bs[kk][tn0 + 4]);
            #pragma unroll
            for (int i = 0; i < 8; i++)
                #pragma unroll
                for (int jj = 0; jj < 8; jj++)
                    acc[i][jj] = fmaf(ar[i], br[jj], acc[i][jj]);
        }
        __syncthreads();
    }

    // epilogue: bias + store
    #pragma unroll
    for (int i = 0; i < 8; i++) {
        int row = bm0 + tm0 + i;
        if (row >= ROWS) break;
        size_t obase = (size_t)row * E_ + ncol0 + tn0;
        #pragma unroll
        for (int jj = 0; jj < 8; jj++)
            outp[obase + jj] = acc[i][jj] + bias[ncol0 + tn0 + jj];
    }
}

// ---------------------------------------------------------------------------
// Kernel 3: window-7 local attention + Lorentz exp-map at origin.
// One block per (bj, t) row, 256 threads (one per channel).
// ---------------------------------------------------------------------------
__global__ void attn_kernel(const float* __restrict__ tau, float* __restrict__ out)
{
    int row = blockIdx.x;          // bj*T + t
    int bj  = row / T_;
    int t   = row - bj * T_;
    int d   = threadIdx.x;
    int lane = d & 31, wid = d >> 5;

    size_t qbase = (size_t)row * E_;
    float qd = g_q[qbase + d];

    int base_row = bj * T_;

    float part[KW_];
    #pragma unroll
    for (int w = 0; w < KW_; w++) {
        int tt = t + w - W_;
        bool valid = (tt >= 0) && (tt < T_);
        part[w] = valid ? qd * g_k[(size_t)(base_row + tt) * E_ + d] : 0.f;
    }

    // block-reduce all 7 partial dots
    #pragma unroll
    for (int w = 0; w < KW_; w++)
        #pragma unroll
        for (int o = 16; o > 0; o >>= 1)
            part[w] += __shfl_xor_sync(0xffffffffu, part[w], o);

    __shared__ float red[KW_][8];
    if (lane == 0) {
        #pragma unroll
        for (int w = 0; w < KW_; w++) red[w][wid] = part[w];
    }
    __syncthreads();

    // every thread computes softmax identically (7 values)
    float inv_scale = 1.0f / (16.0f * fmaxf(tau[0], 0.001f));
    float logit[KW_];
    float m = -1e30f;
    #pragma unroll
    for (int w = 0; w < KW_; w++) {
        int tt = t + w - W_;
        bool valid = (tt >= 0) && (tt < T_);
        float s = 0.f;
        #pragma unroll
        for (int i = 0; i < 8; i++) s += red[w][i];
        logit[w] = valid ? s * inv_scale : -1e30f;
        m = fmaxf(m, logit[w]);
    }
    float esum = 0.f, e[KW_];
    #pragma unroll
    for (int w = 0; w < KW_; w++) {
        int tt = t + w - W_;
        bool valid = (tt >= 0) && (tt < T_);
        e[w] = valid ? __expf(logit[w] - m) : 0.f;
        esum += e[w];
    }
    float inv_esum = 1.0f / esum;

    float agg = 0.f;
    #pragma unroll
    for (int w = 0; w < KW_; w++) {
        int tt = t + w - W_;
        if (tt >= 0 && tt < T_)
            agg = fmaf(e[w] * inv_esum, g_v[(size_t)(base_row + tt) * E_ + d], agg);
    }

    // reduce ||agg||
    float v = agg * agg;
    #pragma unroll
    for (int o = 16; o > 0; o >>= 1) v += __shfl_xor_sync(0xffffffffu, v, o);
    __shared__ float red2[8];
    __syncthreads();                // protect red[] reuse ordering (separate array anyway)
    if (lane == 0) red2[wid] = v;
    __syncthreads();

    __shared__ float n_sh;
    if (d == 0) {
        float tot = 0.f;
        #pragma unroll
        for (int i = 0; i < 8; i++) tot += red2[i];
        n_sh = sqrtf(tot);
    }
    __syncthreads();

    float n = fmaxf(n_sh, 1e-7f);
    float coef = sinhf(n) / n;

    int b = bj / J_;
    int j = bj - b * J_;
    size_t obase = ((size_t)(b * T_ + t) * J_ + j) * D_;
    out[obase + 1 + d] = coef * agg;
    if (d == 0) out[obase] = coshf(n);
}

// ---------------------------------------------------------------------------
extern "C" void kernel_launch(void* const* d_in, const int* in_sizes, int n_in,
                              void* d_out, int out_size)
{
    const float* x    = (const float*)d_in[0];
    // d_in[1] = vel_seq (unused by reference)
    const float* tau  = (const float*)d_in[2];
    const float* Wq   = (const float*)d_in[3];
    const float* bq   = (const float*)d_in[4];
    const float* Wk   = (const float*)d_in[5];
    const float* bk   = (const float*)d_in[6];
    const float* Wv   = (const float*)d_in[7];
    const float* bv   = (const float*)d_in[8];
    float* out = (float*)d_out;

    logmap_kernel<<<ROWS, 256>>>(x);

    dim3 g2((ROWS + BM - 1) / BM, (3 * E_) / BN);
    qkv_gemm<<<g2, 256>>>(Wq, bq, Wk, bk, Wv, bv);

    attn_kernel<<<ROWS, 256>>>(tau, out);
}

// round 3
// speedup vs baseline: 1.5905x; 1.5905x over previous
#include <cuda_runtime.h>
#include <math.h>
#include <stdint.h>

#define B_   16
#define T_   243
#define J_   17
#define D_   257
#define E_   256
#define W_   3
#define KW_  7
#define ROWS (B_ * J_ * T_)   // 66096

// Scratch (no allocation allowed in kernel_launch)
__device__ float g_spatial[(size_t)ROWS * E_];
__device__ float g_q[(size_t)ROWS * E_];
__device__ float g_k[(size_t)ROWS * E_];
__device__ float g_v[(size_t)ROWS * E_];

// ---------------------------------------------------------------------------
// Kernel 1: Lorentz log-map (spatial part) + layout transpose. Warp per row.
// ---------------------------------------------------------------------------
__global__ void logmap_kernel(const float* __restrict__ x)
{
    int gw = blockIdx.x * 8 + (threadIdx.x >> 5);
    if (gw >= ROWS) return;
    int lane = threadIdx.x & 31;

    int bj = gw / T_;
    int t  = gw - bj * T_;
    int b  = bj / J_;
    int j  = bj - b * J_;
    size_t base = ((size_t)(b * T_ + t) * J_ + j) * D_;

    float s8[8];
    float ss = 0.f;
    #pragma unroll
    for (int i = 0; i < 8; i++) {
        s8[i] = x[base + 1 + i * 32 + lane];   // coalesced
        ss = fmaf(s8[i], s8[i], ss);
    }
    #pragma unroll
    for (int o = 16; o > 0; o >>= 1) ss += __shfl_xor_sync(0xffffffffu, ss, o);

    float xn = fmaxf(sqrtf(ss), 1e-7f);
    float xt = x[base];                         // broadcast load
    float scale = acoshf(fmaxf(xt, 1.0f + 1e-7f)) / xn;

    size_t obase = (size_t)gw * E_;
    #pragma unroll
    for (int i = 0; i < 8; i++)
        g_spatial[obase + i * 32 + lane] = scale * s8[i];
}

// ---------------------------------------------------------------------------
// Kernel 2: fused QKV GEMM on tensor cores (tf32 mma, 3xTF32 compensation).
//   out[m,n] = sum_k spatial[m,k] * W[n,k] + bias[n]
//   Block tile 128x128, BK=32, 256 threads (8 warps, 2x4), warp tile 64x32.
// ---------------------------------------------------------------------------
#define GBM 128
#define GBN 128
#define GBK 32
#define SPAD 36

__device__ __forceinline__ void split_tf32(float x, uint32_t& hi, uint32_t& lo)
{
    asm("cvt.rna.tf32.f32 %0, %1;" : "=r"(hi) : "f"(x));
    float r = x - __uint_as_float(hi);
    asm("cvt.rna.tf32.f32 %0, %1;" : "=r"(lo) : "f"(r));
}

__device__ __forceinline__ void mma_tf32(float* c, const uint32_t* a, const uint32_t* b)
{
    asm volatile(
        "mma.sync.aligned.m16n8k8.row.col.f32.tf32.tf32.f32 "
        "{%0,%1,%2,%3}, {%4,%5,%6,%7}, {%8,%9}, {%0,%1,%2,%3};"
        : "+f"(c[0]), "+f"(c[1]), "+f"(c[2]), "+f"(c[3])
        : "r"(a[0]), "r"(a[1]), "r"(a[2]), "r"(a[3]), "r"(b[0]), "r"(b[1]));
}

__global__ __launch_bounds__(256) void qkv_gemm_tc(
    const float* __restrict__ Wq, const float* __restrict__ bq,
    const float* __restrict__ Wk, const float* __restrict__ bk,
    const float* __restrict__ Wv, const float* __restrict__ bv)
{
    __shared__ float As[GBM][SPAD];
    __shared__ float Bs[GBN][SPAD];

    int bm0 = blockIdx.x * GBM;
    int bn0 = blockIdx.y * GBN;           // 0..640
    int which = bn0 >> 8;                 // 0=q,1=k,2=v
    int ncol0 = bn0 & 255;

    const float* Wm   = (which == 0) ? Wq : (which == 1) ? Wk : Wv;
    const float* bias = (which == 0) ? bq : (which == 1) ? bk : bv;
    float*       outp = (which == 0) ? g_q : (which == 1) ? g_k : g_v;

    int tid  = threadIdx.x;
    int w    = tid >> 5;
    int lane = tid & 31;
    int m_off = (w >> 2) * 64;            // 0 / 64
    int n_off = (w & 3) * 32;             // 0/32/64/96

    int lg = lane >> 2;                   // groupID 0..7
    int lt = lane & 3;                    // threadID_in_group 0..3

    float acc[4][4][4];
    #pragma unroll
    for (int mi = 0; mi < 4; mi++)
        #pragma unroll
        for (int ni = 0; ni < 4; ni++)
            #pragma unroll
            for (int c = 0; c < 4; c++) acc[mi][ni][c] = 0.f;

    for (int k0 = 0; k0 < E_; k0 += GBK) {
        // load A & B tiles: 1024 float4 each, 4 per thread
        #pragma unroll
        for (int r = 0; r < 4; r++) {
            int i  = tid + 256 * r;
            int m  = i >> 3;
            int kq = (i & 7) * 4;
            float4 av = make_float4(0.f, 0.f, 0.f, 0.f);
            if (bm0 + m < ROWS)
                av = *reinterpret_cast<const float4*>(&g_spatial[(size_t)(bm0 + m) * E_ + k0 + kq]);
            *reinterpret_cast<float4*>(&As[m][kq]) = av;
            float4 bv4 = *reinterpret_cast<const float4*>(&Wm[(size_t)(ncol0 + m) * E_ + k0 + kq]);
            *reinterpret_cast<float4*>(&Bs[m][kq]) = bv4;
        }
        __syncthreads();

        #pragma unroll
        for (int kk = 0; kk < GBK; kk += 8) {
            // A fragment register order (PTX m16n8k8 tf32):
            //   a0=(row g,   col t)   a1=(row g+8, col t)
            //   a2=(row g,   col t+4) a3=(row g+8, col t+4)
            uint32_t ahi[4][4], alo[4][4];
            #pragma unroll
            for (int mi = 0; mi < 4; mi++) {
                int r0 = m_off + mi * 16 + lg;
                split_tf32(As[r0    ][kk + lt    ], ahi[mi][0], alo[mi][0]);
                split_tf32(As[r0 + 8][kk + lt    ], ahi[mi][1], alo[mi][1]);
                split_tf32(As[r0    ][kk + lt + 4], ahi[mi][2], alo[mi][2]);
                split_tf32(As[r0 + 8][kk + lt + 4], ahi[mi][3], alo[mi][3]);
            }
            uint32_t bhi[4][2], blo[4][2];
            #pragma unroll
            for (int ni = 0; ni < 4; ni++) {
                int c0 = n_off + ni * 8 + lg;
                split_tf32(Bs[c0][kk + lt    ], bhi[ni][0], blo[ni][0]);
                split_tf32(Bs[c0][kk + lt + 4], bhi[ni][1], blo[ni][1]);
            }
            #pragma unroll
            for (int mi = 0; mi < 4; mi++)
                #pragma unroll
                for (int ni = 0; ni < 4; ni++) {
                    mma_tf32(acc[mi][ni], ahi[mi], bhi[ni]);
                    mma_tf32(acc[mi][ni], ahi[mi], blo[ni]);
                    mma_tf32(acc[mi][ni], alo[mi], bhi[ni]);
                }
        }
        __syncthreads();
    }

    // epilogue: bias + store
    #pragma unroll
    for (int mi = 0; mi < 4; mi++) {
        int row0 = bm0 + m_off + mi * 16 + lg;
        #pragma unroll
        for (int ni = 0; ni < 4; ni++) {
            int col = ncol0 + n_off + ni * 8 + lt * 2;
            float b0 = bias[col], b1 = bias[col + 1];
            if (row0 < ROWS) {
                outp[(size_t)row0 * E_ + col]     = acc[mi][ni][0] + b0;
                outp[(size_t)row0 * E_ + col + 1] = acc[mi][ni][1] + b1;
            }
            if (row0 + 8 < ROWS) {
                outp[(size_t)(row0 + 8) * E_ + col]     = acc[mi][ni][2] + b0;
                outp[(size_t)(row0 + 8) * E_ + col + 1] = acc[mi][ni][3] + b1;
            }
        }
    }
}

// ---------------------------------------------------------------------------
// Kernel 3: window-7 local attention + Lorentz exp-map. Warp per row.
// ---------------------------------------------------------------------------
__global__ void attn_kernel(const float* __restrict__ tau, float* __restrict__ out)
{
    int gw = blockIdx.x * 8 + (threadIdx.x >> 5);
    if (gw >= ROWS) return;
    int lane = threadIdx.x & 31;

    int bj = gw / T_;
    int t  = gw - bj * T_;
    int base_row = bj * T_;

    size_t qoff = (size_t)gw * E_ + lane * 8;
    float4 q0 = *reinterpret_cast<const float4*>(&g_q[qoff]);
    float4 q1 = *reinterpret_cast<const float4*>(&g_q[qoff + 4]);

    float dot[KW_];
    #pragma unroll
    for (int w = 0; w < KW_; w++) {
        int tt = t + w - W_;
        float d = 0.f;
        if (tt >= 0 && tt < T_) {
            size_t koff = (size_t)(base_row + tt) * E_ + lane * 8;
            float4 k0 = *reinterpret_cast<const float4*>(&g_k[koff]);
            float4 k1 = *reinterpret_cast<const float4*>(&g_k[koff + 4]);
            d = q0.x * k0.x + q0.y * k0.y + q0.z * k0.z + q0.w * k0.w
              + q1.x * k1.x + q1.y * k1.y + q1.z * k1.z + q1.w * k1.w;
        }
        #pragma unroll
        for (int o = 16; o > 0; o >>= 1) d += __shfl_xor_sync(0xffffffffu, d, o);
        dot[w] = d;
    }

    // softmax over the 7 window slots (all lanes compute identically)
    float inv_scale = 1.0f / (16.0f * fmaxf(tau[0], 0.001f));
    float m = -1e30f;
    float logit[KW_];
    #pragma unroll
    for (int w = 0; w < KW_; w++) {
        int tt = t + w - W_;
        bool valid = (tt >= 0) && (tt < T_);
        logit[w] = valid ? dot[w] * inv_scale : -1e30f;
        m = fmaxf(m, logit[w]);
    }
    float e[KW_], esum = 0.f;
    #pragma unroll
    for (int w = 0; w < KW_; w++) {
        int tt = t + w - W_;
        bool valid = (tt >= 0) && (tt < T_);
        e[w] = valid ? __expf(logit[w] - m) : 0.f;
        esum += e[w];
    }
    float inv_esum = 1.0f / esum;

    float agg[8] = {0.f, 0.f, 0.f, 0.f, 0.f, 0.f, 0.f, 0.f};
    #pragma unroll
    for (int w = 0; w < KW_; w++) {
        int tt = t + w - W_;
        if (tt >= 0 && tt < T_) {
            float wt = e[w] * inv_esum;
            size_t voff = (size_t)(base_row + tt) * E_ + lane * 8;
            float4 v0 = *reinterpret_cast<const float4*>(&g_v[voff]);
            float4 v1 = *reinterpret_cast<const float4*>(&g_v[voff + 4]);
            agg[0] = fmaf(wt, v0.x, agg[0]); agg[1] = fmaf(wt, v0.y, agg[1]);
            agg[2] = fmaf(wt, v0.z, agg[2]); agg[3] = fmaf(wt, v0.w, agg[3]);
            agg[4] = fmaf(wt, v1.x, agg[4]); agg[5] = fmaf(wt, v1.y, agg[5]);
            agg[6] = fmaf(wt, v1.z, agg[6]); agg[7] = fmaf(wt, v1.w, agg[7]);
        }
    }

    float ss = 0.f;
    #pragma unroll
    for (int i = 0; i < 8; i++) ss = fmaf(agg[i], agg[i], ss);
    #pragma unroll
    for (int o = 16; o > 0; o >>= 1) ss += __shfl_xor_sync(0xffffffffu, ss, o);

    float n = fmaxf(sqrtf(ss), 1e-7f);
    float coef = sinhf(n) / n;

    int b = bj / J_;
    int j = bj - b * J_;
    size_t obase = ((size_t)(b * T_ + t) * J_ + j) * D_;
    #pragma unroll
    for (int i = 0; i < 8; i++)
        out[obase + 1 + lane * 8 + i] = coef * agg[i];
    if (lane == 0) out[obase] = coshf(sqrtf(ss));
}

// ---------------------------------------------------------------------------
extern "C" void kernel_launch(void* const* d_in, const int* in_sizes, int n_in,
                              void* d_out, int out_size)
{
    const float* x    = (const float*)d_in[0];
    // d_in[1] = vel_seq (unused by reference)
    const float* tau  = (const float*)d_in[2];
    const float* Wq   = (const float*)d_in[3];
    const float* bq   = (const float*)d_in[4];
    const float* Wk   = (const float*)d_in[5];
    const float* bk   = (const float*)d_in[6];
    const float* Wv   = (const float*)d_in[7];
    const float* bv   = (const float*)d_in[8];
    float* out = (float*)d_out;

    int rowblocks = (ROWS + 7) / 8;   // 8 warps (rows) per 256-thread block

    logmap_kernel<<<rowblocks, 256>>>(x);

    dim3 g2((ROWS + GBM - 1) / GBM, (3 * E_) / GBN);
    qkv_gemm_tc<<<g2, 256>>>(Wq, bq, Wk, bk, Wv, bv);

    attn_kernel<<<rowblocks, 256>>>(tau, out);
}

// round 4
// speedup vs baseline: 2.4095x; 1.5149x over previous
#include <cuda_runtime.h>
#include <cuda_bf16.h>
#include <math.h>
#include <stdint.h>

#define B_   16
#define T_   243
#define J_   17
#define D_   257
#define E_   256
#define W_   3
#define KW_  7
#define ROWS (B_ * J_ * T_)   // 66096

// Scratch (no allocation allowed)
__device__ __nv_bfloat16 g_s_hi[(size_t)ROWS * E_];
__device__ __nv_bfloat16 g_s_lo[(size_t)ROWS * E_];
__device__ __nv_bfloat16 g_w_hi[3 * E_ * E_];
__device__ __nv_bfloat16 g_w_lo[3 * E_ * E_];
__device__ float g_q[(size_t)ROWS * E_];
__device__ float g_k[(size_t)ROWS * E_];
__device__ float g_v[(size_t)ROWS * E_];

__device__ __forceinline__ void split_bf16(float x, __nv_bfloat16& hi, __nv_bfloat16& lo)
{
    hi = __float2bfloat16_rn(x);
    lo = __float2bfloat16_rn(x - __bfloat162float(hi));
}

// ---------------------------------------------------------------------------
// Kernel 0: pre-split weight matrices into bf16 hi/lo planes.
// ---------------------------------------------------------------------------
__global__ void wsplit_kernel(const float* __restrict__ Wq,
                              const float* __restrict__ Wk,
                              const float* __restrict__ Wv)
{
    int i = blockIdx.x * 256 + threadIdx.x;   // 0 .. 65535
    __nv_bfloat16 h, l;
    split_bf16(Wq[i], h, l); g_w_hi[i] = h;             g_w_lo[i] = l;
    split_bf16(Wk[i], h, l); g_w_hi[E_*E_ + i] = h;     g_w_lo[E_*E_ + i] = l;
    split_bf16(Wv[i], h, l); g_w_hi[2*E_*E_ + i] = h;   g_w_lo[2*E_*E_ + i] = l;
}

// ---------------------------------------------------------------------------
// Kernel 1: Lorentz log-map + transpose + bf16 hi/lo split. Warp per row.
// ---------------------------------------------------------------------------
__global__ void logmap_kernel(const float* __restrict__ x)
{
    int gw = blockIdx.x * 8 + (threadIdx.x >> 5);
    if (gw >= ROWS) return;
    int lane = threadIdx.x & 31;

    int bj = gw / T_;
    int t  = gw - bj * T_;
    int b  = bj / J_;
    int j  = bj - b * J_;
    size_t base = ((size_t)(b * T_ + t) * J_ + j) * D_;

    float s8[8];
    float ss = 0.f;
    #pragma unroll
    for (int i = 0; i < 8; i++) {
        s8[i] = x[base + 1 + i * 32 + lane];
        ss = fmaf(s8[i], s8[i], ss);
    }
    #pragma unroll
    for (int o = 16; o > 0; o >>= 1) ss += __shfl_xor_sync(0xffffffffu, ss, o);

    float xn = fmaxf(sqrtf(ss), 1e-7f);
    float xt = x[base];
    float scale = acoshf(fmaxf(xt, 1.0f + 1e-7f)) / xn;

    size_t obase = (size_t)gw * E_;
    #pragma unroll
    for (int i = 0; i < 8; i++) {
        float v = scale * s8[i];
        __nv_bfloat16 h, l;
        split_bf16(v, h, l);
        g_s_hi[obase + i * 32 + lane] = h;
        g_s_lo[obase + i * 32 + lane] = l;
    }
}

// ---------------------------------------------------------------------------
// Kernel 2: fused QKV GEMM, bf16 tensor cores, 3xBF16 error compensation.
//   out[m,n] = sum_k s[m,k]*W[n,k] + bias[n]
//   Block 128x128, GBK=32, 256 thr (8 warps 2x4), warp tile 64x32, mma k16.
//   smem planes: row stride 20 uint32 (40 bf16, 80 B) -> conflict-free frags.
// ---------------------------------------------------------------------------
#define GBM 128
#define GBN 128
#define GBK 32
#define RS  20   // row stride in uint32

__device__ __forceinline__ void mma_bf16(float* c, const uint32_t* a, const uint32_t* b)
{
    asm volatile(
        "mma.sync.aligned.m16n8k16.row.col.f32.bf16.bf16.f32 "
        "{%0,%1,%2,%3}, {%4,%5,%6,%7}, {%8,%9}, {%0,%1,%2,%3};"
        : "+f"(c[0]), "+f"(c[1]), "+f"(c[2]), "+f"(c[3])
        : "r"(a[0]), "r"(a[1]), "r"(a[2]), "r"(a[3]), "r"(b[0]), "r"(b[1]));
}

__global__ __launch_bounds__(256) void qkv_gemm_tc(
    const float* __restrict__ bq, const float* __restrict__ bk,
    const float* __restrict__ bv)
{
    __shared__ __align__(16) uint32_t As_hi[GBM * RS];
    __shared__ __align__(16) uint32_t As_lo[GBM * RS];
    __shared__ __align__(16) uint32_t Bs_hi[GBN * RS];
    __shared__ __align__(16) uint32_t Bs_lo[GBN * RS];

    int bn0 = blockIdx.x * GBN;           // fast dim: N (6 tiles share A in L2)
    int bm0 = blockIdx.y * GBM;
    int which = bn0 >> 8;                 // 0=q,1=k,2=v
    int ncol0 = bn0 & 255;

    const __nv_bfloat16* Whi = g_w_hi + (size_t)which * E_ * E_;
    const __nv_bfloat16* Wlo = g_w_lo + (size_t)which * E_ * E_;
    const float* bias = (which == 0) ? bq : (which == 1) ? bk : bv;
    float*       outp = (which == 0) ? g_q : (which == 1) ? g_k : g_v;

    int tid  = threadIdx.x;
    int w    = tid >> 5;
    int lane = tid & 31;
    int m_off = (w >> 2) * 64;            // 0 / 64
    int n_off = (w & 3) * 32;             // 0/32/64/96
    int lg = lane >> 2;                   // 0..7
    int lt = lane & 3;                    // 0..3

    float acc[4][4][4];
    #pragma unroll
    for (int mi = 0; mi < 4; mi++)
        #pragma unroll
        for (int ni = 0; ni < 4; ni++)
            #pragma unroll
            for (int c = 0; c < 4; c++) acc[mi][ni][c] = 0.f;

    for (int k0 = 0; k0 < E_; k0 += GBK) {
        // stage tiles: each plane 128 rows x 32 bf16; uint4 = 8 bf16
        #pragma unroll
        for (int r = 0; r < 2; r++) {
            int u = tid + 256 * r;        // 0..511
            int m = u >> 2;               // 0..127
            int q = u & 3;                // uint4 within row
            size_t ga = (size_t)(bm0 + m) * E_ + k0 + q * 8;
            uint4 z = make_uint4(0u, 0u, 0u, 0u);
            uint4 ah = z, al = z;
            if (bm0 + m < ROWS) {
                ah = *reinterpret_cast<const uint4*>(&g_s_hi[ga]);
                al = *reinterpret_cast<const uint4*>(&g_s_lo[ga]);
            }
            *reinterpret_cast<uint4*>(&As_hi[m * RS + q * 4]) = ah;
            *reinterpret_cast<uint4*>(&As_lo[m * RS + q * 4]) = al;

            size_t gb = (size_t)(ncol0 + m) * E_ + k0 + q * 8;
            *reinterpret_cast<uint4*>(&Bs_hi[m * RS + q * 4]) =
                *reinterpret_cast<const uint4*>(&Whi[gb]);
            *reinterpret_cast<uint4*>(&Bs_lo[m * RS + q * 4]) =
                *reinterpret_cast<const uint4*>(&Wlo[gb]);
        }
        __syncthreads();

        #pragma unroll
        for (int ks = 0; ks < 2; ks++) {  // two k16 steps per GBK=32
            int kb = ks * 8;
            uint32_t a_h[4][4], a_l[4][4];
            #pragma unroll
            for (int mi = 0; mi < 4; mi++) {
                int r0 = (m_off + mi * 16 + lg) * RS + kb;
                a_h[mi][0] = As_hi[r0 + lt];
                a_h[mi][1] = As_hi[r0 + 8 * RS + lt];
                a_h[mi][2] = As_hi[r0 + lt + 4];
                a_h[mi][3] = As_hi[r0 + 8 * RS + lt + 4];
                a_l[mi][0] = As_lo[r0 + lt];
                a_l[mi][1] = As_lo[r0 + 8 * RS + lt];
                a_l[mi][2] = As_lo[r0 + lt + 4];
                a_l[mi][3] = As_lo[r0 + 8 * RS + lt + 4];
            }
            uint32_t b_h[4][2], b_l[4][2];
            #pragma unroll
            for (int ni = 0; ni < 4; ni++) {
                int c0 = (n_off + ni * 8 + lg) * RS + kb;
                b_h[ni][0] = Bs_hi[c0 + lt];
                b_h[ni][1] = Bs_hi[c0 + lt + 4];
                b_l[ni][0] = Bs_lo[c0 + lt];
                b_l[ni][1] = Bs_lo[c0 + lt + 4];
            }
            #pragma unroll
            for (int mi = 0; mi < 4; mi++)
                #pragma unroll
                for (int ni = 0; ni < 4; ni++) {
                    mma_bf16(acc[mi][ni], a_h[mi], b_h[ni]);
                    mma_bf16(acc[mi][ni], a_h[mi], b_l[ni]);
                    mma_bf16(acc[mi][ni], a_l[mi], b_h[ni]);
                }
        }
        __syncthreads();
    }

    // epilogue: bias + store (C frag: c0,c1 = row lg cols 2lt,2lt+1; c2,c3 = row lg+8)
    #pragma unroll
    for (int mi = 0; mi < 4; mi++) {
        int row0 = bm0 + m_off + mi * 16 + lg;
        #pragma unroll
        for (int ni = 0; ni < 4; ni++) {
            int col = ncol0 + n_off + ni * 8 + lt * 2;
            float b0 = bias[col], b1 = bias[col + 1];
            if (row0 < ROWS) {
                outp[(size_t)row0 * E_ + col]     = acc[mi][ni][0] + b0;
                outp[(size_t)row0 * E_ + col + 1] = acc[mi][ni][1] + b1;
            }
            if (row0 + 8 < ROWS) {
                outp[(size_t)(row0 + 8) * E_ + col]     = acc[mi][ni][2] + b0;
                outp[(size_t)(row0 + 8) * E_ + col + 1] = acc[mi][ni][3] + b1;
            }
        }
    }
}

// ---------------------------------------------------------------------------
// Kernel 3: window-7 attention + exp-map, smem-tiled over t.
//   Block = one (bj, 16-t tile). K/V strips (22 rows) staged in smem.
// ---------------------------------------------------------------------------
#define TT 16
#define STRIP (TT + 2 * W_)   // 22

__global__ __launch_bounds__(256) void attn_kernel(const float* __restrict__ tau,
                                                   float* __restrict__ out)
{
    __shared__ float sK[STRIP * E_];
    __shared__ float sV[STRIP * E_];

    int t0 = blockIdx.x * TT;
    int bj = blockIdx.y;
    int base_row = bj * T_;
    int tid = threadIdx.x;

    // stage K/V strips (rows t0-3 .. t0+18, clamped)
    for (int i = tid; i < STRIP * (E_ / 4); i += 256) {
        int r  = i >> 6;          // strip row
        int c4 = i & 63;
        int tt = t0 - W_ + r;
        tt = min(max(tt, 0), T_ - 1);
        size_t g = (size_t)(base_row + tt) * E_ + c4 * 4;
        *reinterpret_cast<float4*>(&sK[r * E_ + c4 * 4]) =
            *reinterpret_cast<const float4*>(&g_k[g]);
        *reinterpret_cast<float4*>(&sV[r * E_ + c4 * 4]) =
            *reinterpret_cast<const float4*>(&g_v[g]);
    }
    __syncthreads();

    int warp = tid >> 5, lane = tid & 31;
    float inv_scale = 1.0f / (16.0f * fmaxf(tau[0], 0.001f));

    #pragma unroll
    for (int s = 0; s < 2; s++) {
        int t = t0 + warp * 2 + s;
        if (t >= T_) continue;
        int lrow = t - t0;        // smem row for w: lrow + w

        size_t qoff = (size_t)(base_row + t) * E_ + lane * 8;
        float4 q0 = *reinterpret_cast<const float4*>(&g_q[qoff]);
        float4 q1 = *reinterpret_cast<const float4*>(&g_q[qoff + 4]);

        float dot[KW_];
        #pragma unroll
        for (int w = 0; w < KW_; w++) {
            const float* kr = &sK[(lrow + w) * E_ + lane * 8];
            float4 k0 = *reinterpret_cast<const float4*>(kr);
            float4 k1 = *reinterpret_cast<const float4*>(kr + 4);
            float d = q0.x * k0.x + q0.y * k0.y + q0.z * k0.z + q0.w * k0.w
                    + q1.x * k1.x + q1.y * k1.y + q1.z * k1.z + q1.w * k1.w;
            #pragma unroll
            for (int o = 16; o > 0; o >>= 1) d += __shfl_xor_sync(0xffffffffu, d, o);
            dot[w] = d;
        }

        float m = -1e30f, logit[KW_];
        #pragma unroll
        for (int w = 0; w < KW_; w++) {
            int tt = t + w - W_;
            bool valid = (tt >= 0) && (tt < T_);
            logit[w] = valid ? dot[w] * inv_scale : -1e30f;
            m = fmaxf(m, logit[w]);
        }
        float e[KW_], esum = 0.f;
        #pragma unroll
        for (int w = 0; w < KW_; w++) {
            int tt = t + w - W_;
            bool valid = (tt >= 0) && (tt < T_);
            e[w] = valid ? __expf(logit[w] - m) : 0.f;
            esum += e[w];
        }
        float inv_esum = 1.0f / esum;

        float agg[8] = {0.f, 0.f, 0.f, 0.f, 0.f, 0.f, 0.f, 0.f};
        #pragma unroll
        for (int w = 0; w < KW_; w++) {
            int tt = t + w - W_;
            if (tt >= 0 && tt < T_) {
                float wt = e[w] * inv_esum;
                const float* vr = &sV[(lrow + w) * E_ + lane * 8];
                float4 v0 = *reinterpret_cast<const float4*>(vr);
                float4 v1 = *reinterpret_cast<const float4*>(vr + 4);
                agg[0] = fmaf(wt, v0.x, agg[0]); agg[1] = fmaf(wt, v0.y, agg[1]);
                agg[2] = fmaf(wt, v0.z, agg[2]); agg[3] = fmaf(wt, v0.w, agg[3]);
                agg[4] = fmaf(wt, v1.x, agg[4]); agg[5] = fmaf(wt, v1.y, agg[5]);
                agg[6] = fmaf(wt, v1.z, agg[6]); agg[7] = fmaf(wt, v1.w, agg[7]);
            }
        }

        float ss = 0.f;
        #pragma unroll
        for (int i = 0; i < 8; i++) ss = fmaf(agg[i], agg[i], ss);
        #pragma unroll
        for (int o = 16; o > 0; o >>= 1) ss += __shfl_xor_sync(0xffffffffu, ss, o);

        float n = fmaxf(sqrtf(ss), 1e-7f);
        float coef = sinhf(n) / n;

        int b = bj / J_;
        int j = bj - b * J_;
        size_t obase = ((size_t)(b * T_ + t) * J_ + j) * D_;
        #pragma unroll
        for (int i = 0; i < 8; i++)
            out[obase + 1 + lane * 8 + i] = coef * agg[i];
        if (lane == 0) out[obase] = coshf(sqrtf(ss));
    }
}

// ---------------------------------------------------------------------------
extern "C" void kernel_launch(void* const* d_in, const int* in_sizes, int n_in,
                              void* d_out, int out_size)
{
    const float* x    = (const float*)d_in[0];
    // d_in[1] = vel_seq (unused by reference)
    const float* tau  = (const float*)d_in[2];
    const float* Wq   = (const float*)d_in[3];
    const float* bq   = (const float*)d_in[4];
    const float* Wk   = (const float*)d_in[5];
    const float* bk   = (const float*)d_in[6];
    const float* Wv   = (const float*)d_in[7];
    const float* bv   = (const float*)d_in[8];
    float* out = (float*)d_out;

    wsplit_kernel<<<E_ * E_ / 256, 256>>>(Wq, Wk, Wv);
    logmap_kernel<<<(ROWS + 7) / 8, 256>>>(x);

    dim3 g2((3 * E_) / GBN, (ROWS + GBM - 1) / GBM);   // N fast -> A reuse in L2
    qkv_gemm_tc<<<g2, 256>>>(bq, bk, bv);

    dim3 g3((T_ + TT - 1) / TT, B_ * J_);
    attn_kernel<<<g3, 256>>>(tau, out);
}

// round 7
// speedup vs baseline: 2.7118x; 1.1255x over previous
#include <cuda_runtime.h>
#include <cuda_bf16.h>
#include <math.h>
#include <stdint.h>

#define B_   16
#define T_   243
#define J_   17
#define D_   257
#define E_   256
#define W_   3
#define KW_  7
#define ROWS (B_ * T_ * J_)   // 66096
#define MTILES ((ROWS + 127) / 128)   // 517

// Scratch
__device__ __nv_bfloat16 g_s_hi[(size_t)ROWS * E_];
__device__ __nv_bfloat16 g_s_lo[(size_t)ROWS * E_];
__device__ __nv_bfloat16 g_w_hi[3 * E_ * E_];
__device__ __nv_bfloat16 g_w_lo[3 * E_ * E_];
__device__ float g_q[(size_t)ROWS * E_];
__device__ float g_k[(size_t)ROWS * E_];
__device__ float g_v[(size_t)ROWS * E_];

__device__ __forceinline__ void split_bf16(float x, __nv_bfloat16& hi, __nv_bfloat16& lo)
{
    hi = __float2bfloat16_rn(x);
    lo = __float2bfloat16_rn(x - __bfloat162float(hi));
}

// ---------------------------------------------------------------------------
// Kernel 0: pre-split weights into bf16 hi/lo planes.
// ---------------------------------------------------------------------------
__global__ void wsplit_kernel(const float* __restrict__ Wq,
                              const float* __restrict__ Wk,
                              const float* __restrict__ Wv)
{
    int i = blockIdx.x * 256 + threadIdx.x;
    __nv_bfloat16 h, l;
    split_bf16(Wq[i], h, l); g_w_hi[i] = h;             g_w_lo[i] = l;
    split_bf16(Wk[i], h, l); g_w_hi[E_*E_ + i] = h;     g_w_lo[E_*E_ + i] = l;
    split_bf16(Wv[i], h, l); g_w_hi[2*E_*E_ + i] = h;   g_w_lo[2*E_*E_ + i] = l;
}

// ---------------------------------------------------------------------------
// Kernel 1: Lorentz log-map + transpose + bf16 hi/lo split. Warp per row.
// ---------------------------------------------------------------------------
__global__ void logmap_kernel(const float* __restrict__ x)
{
    int gw = blockIdx.x * 8 + (threadIdx.x >> 5);
    if (gw >= ROWS) return;
    int lane = threadIdx.x & 31;

    int bj = gw / T_;
    int t  = gw - bj * T_;
    int b  = bj / J_;
    int j  = bj - b * J_;
    size_t base = ((size_t)(b * T_ + t) * J_ + j) * D_;

    float s8[8];
    float ss = 0.f;
    #pragma unroll
    for (int i = 0; i < 8; i++) {
        s8[i] = x[base + 1 + i * 32 + lane];
        ss = fmaf(s8[i], s8[i], ss);
    }
    #pragma unroll
    for (int o = 16; o > 0; o >>= 1) ss += __shfl_xor_sync(0xffffffffu, ss, o);

    float xn = fmaxf(sqrtf(ss), 1e-7f);
    float xt = x[base];
    float scale = acoshf(fmaxf(xt, 1.0f + 1e-7f)) / xn;

    size_t obase = (size_t)gw * E_;
    #pragma unroll
    for (int i = 0; i < 8; i++) {
        float v = scale * s8[i];
        __nv_bfloat16 h, l;
        split_bf16(v, h, l);
        g_s_hi[obase + i * 32 + lane] = h;
        g_s_lo[obase + i * 32 + lane] = l;
    }
}

// ---------------------------------------------------------------------------
// Kernel 2: fused QKV GEMM, bf16 mma.sync + ldmatrix + cp.async double buffer.
//   out[m,n] = sum_k s[m,k]*W[n,k] + bias[n]; 3xBF16 compensation.
//   CTA tile 128x128, GBK=64, 256 thr (8 warps 2x4), warp tile 64x32.
//   smem rows padded to 144B (72 bf16) -> conflict-free LDSM & stores.
// ---------------------------------------------------------------------------
#define GSTR   144                    // bytes per smem row
#define PLANE  (128 * GSTR)           // 18432 B per plane (128 rows x 64 bf16)
#define BUFSZ  (4 * PLANE)            // Ahi, Alo, Bhi, Blo
#define GEMM_SMEM (2 * BUFSZ)         // double buffered: 147456 B

__device__ __forceinline__ void mma_bf16(float* c, const uint32_t* a, const uint32_t* b)
{
    asm volatile(
        "mma.sync.aligned.m16n8k16.row.col.f32.bf16.bf16.f32 "
        "{%0,%1,%2,%3}, {%4,%5,%6,%7}, {%8,%9}, {%0,%1,%2,%3};"
        : "+f"(c[0]), "+f"(c[1]), "+f"(c[2]), "+f"(c[3])
        : "r"(a[0]), "r"(a[1]), "r"(a[2]), "r"(a[3]), "r"(b[0]), "r"(b[1]));
}

__device__ __forceinline__ void ldsm4(uint32_t* r, uint32_t a)
{
    asm volatile("ldmatrix.sync.aligned.m8n8.x4.shared.b16 {%0,%1,%2,%3}, [%4];"
                 : "=r"(r[0]), "=r"(r[1]), "=r"(r[2]), "=r"(r[3]) : "r"(a));
}

__device__ __forceinline__ void cp16(uint32_t dst, const void* src, uint32_t sz)
{
    asm volatile("cp.async.cg.shared.global [%0], [%1], 16, %2;"
                 :: "r"(dst), "l"(src), "r"(sz) : "memory");
}

__global__ __launch_bounds__(256) void qkv_gemm_tc(
    const float* __restrict__ bq, const float* __restrict__ bk,
    const float* __restrict__ bv)
{
    extern __shared__ char dynsm[];
    uint32_t smem = (uint32_t)__cvta_generic_to_shared(dynsm);

    int bn0 = blockIdx.x * 128;           // fast dim: N (6 tiles share A in L2)
    int bm0 = blockIdx.y * 128;
    int which = bn0 >> 8;                 // 0=q,1=k,2=v
    int ncol0 = bn0 & 255;

    const __nv_bfloat16* Whi = g_w_hi + (size_t)which * E_ * E_;
    const __nv_bfloat16* Wlo = g_w_lo + (size_t)which * E_ * E_;
    const float* bias = (which == 0) ? bq : (which == 1) ? bk : bv;
    float*       outp = (which == 0) ? g_q : (which == 1) ? g_k : g_v;

    int tid  = threadIdx.x;
    int w    = tid >> 5;
    int lane = tid & 31;
    int m_off = (w >> 2) * 64;            // 0 / 64
    int n_off = (w & 3) * 32;             // 0/32/64/96
    int lg = lane >> 2;                   // 0..7
    int lt = lane & 3;                    // 0..3

    // per-lane ldmatrix row offsets (byte offsets within a plane)
    int sub = lane >> 3;                  // 0..3 (x4 sub-matrix owner)
    int r8  = lane & 7;
    uint32_t aoff[4], boff[2];
    #pragma unroll
    for (int mi = 0; mi < 4; mi++)
        aoff[mi] = (uint32_t)((m_off + mi * 16 + (sub & 1) * 8 + r8) * GSTR
                              + (sub >> 1) * 16);
    #pragma unroll
    for (int nt = 0; nt < 2; nt++)
        boff[nt] = (uint32_t)((n_off + nt * 16 + (sub >> 1) * 8 + r8) * GSTR
                              + (sub & 1) * 16);

    float acc[4][4][4];
    #pragma unroll
    for (int mi = 0; mi < 4; mi++)
        #pragma unroll
        for (int ni = 0; ni < 4; ni++)
            #pragma unroll
            for (int c = 0; c < 4; c++) acc[mi][ni][c] = 0.f;

    // ---- prefetch helper ----
    auto prefetch = [&](int it) {
        uint32_t buf = smem + (uint32_t)(it & 1) * BUFSZ;
        int k0 = it * 64;
        #pragma unroll
        for (int r = 0; r < 4; r++) {
            int idx = tid + 256 * r;
            int row = idx >> 3;
            int q   = idx & 7;
            uint32_t doff = (uint32_t)(row * GSTR + q * 16);
            int grow = bm0 + row;
            uint32_t sz = (grow < ROWS) ? 16u : 0u;
            int ar = (grow < ROWS) ? grow : (ROWS - 1);
            size_t ga = (size_t)ar * E_ + k0 + q * 8;
            cp16(buf + doff,              &g_s_hi[ga], sz);
            cp16(buf + PLANE + doff,      &g_s_lo[ga], sz);
            size_t gb = (size_t)(ncol0 + row) * E_ + k0 + q * 8;   // FIX: +ncol0
            cp16(buf + 2 * PLANE + doff,  &Whi[gb], 16u);
            cp16(buf + 3 * PLANE + doff,  &Wlo[gb], 16u);
        }
        asm volatile("cp.async.commit_group;" ::: "memory");
    };

    prefetch(0);

    #pragma unroll 1
    for (int c = 0; c < 4; c++) {
        if (c < 3) prefetch(c + 1);
        if (c < 3) asm volatile("cp.async.wait_group 1;" ::: "memory");
        else       asm volatile("cp.async.wait_group 0;" ::: "memory");
        __syncthreads();

        uint32_t buf = smem + (uint32_t)(c & 1) * BUFSZ;
        uint32_t Ah = buf, Al = buf + PLANE, Bh = buf + 2 * PLANE, Bl = buf + 3 * PLANE;

        #pragma unroll
        for (int ks = 0; ks < 4; ks++) {
            uint32_t kadd = (uint32_t)(ks * 32);   // 16 bf16 = 32 bytes
            uint32_t ah[4][4], al[4][4];
            #pragma unroll
            for (int mi = 0; mi < 4; mi++) {
                ldsm4(ah[mi], Ah + aoff[mi] + kadd);
                ldsm4(al[mi], Al + aoff[mi] + kadd);
            }
            uint32_t bh[4][2], bl[4][2];
            #pragma unroll
            for (int nt = 0; nt < 2; nt++) {
                uint32_t tmp[4];
                ldsm4(tmp, Bh + boff[nt] + kadd);
                bh[nt*2][0] = tmp[0]; bh[nt*2][1] = tmp[1];
                bh[nt*2+1][0] = tmp[2]; bh[nt*2+1][1] = tmp[3];
                ldsm4(tmp, Bl + boff[nt] + kadd);
                bl[nt*2][0] = tmp[0]; bl[nt*2][1] = tmp[1];
                bl[nt*2+1][0] = tmp[2]; bl[nt*2+1][1] = tmp[3];
            }
            #pragma unroll
            for (int mi = 0; mi < 4; mi++)
                #pragma unroll
                for (int ni = 0; ni < 4; ni++) {
                    mma_bf16(acc[mi][ni], ah[mi], bh[ni]);
                    mma_bf16(acc[mi][ni], ah[mi], bl[ni]);
                    mma_bf16(acc[mi][ni], al[mi], bh[ni]);
                }
        }
        __syncthreads();
    }

    // epilogue: bias + store (c0,c1 = row lg; c2,c3 = row lg+8)
    #pragma unroll
    for (int mi = 0; mi < 4; mi++) {
        int row0 = bm0 + m_off + mi * 16 + lg;
        #pragma unroll
        for (int ni = 0; ni < 4; ni++) {
            int col = ncol0 + n_off + ni * 8 + lt * 2;
            float b0 = bias[col], b1 = bias[col + 1];
            if (row0 < ROWS) {
                outp[(size_t)row0 * E_ + col]     = acc[mi][ni][0] + b0;
                outp[(size_t)row0 * E_ + col + 1] = acc[mi][ni][1] + b1;
            }
            if (row0 + 8 < ROWS) {
                outp[(size_t)(row0 + 8) * E_ + col]     = acc[mi][ni][2] + b0;
                outp[(size_t)(row0 + 8) * E_ + col + 1] = acc[mi][ni][3] + b1;
            }
        }
    }
}

// ---------------------------------------------------------------------------
// Kernel 3: window-7 attention + exp-map, smem-tiled over t. (unchanged)
// ---------------------------------------------------------------------------
#define TT 16
#define STRIP (TT + 2 * W_)   // 22

__global__ __launch_bounds__(256) void attn_kernel(const float* __restrict__ tau,
                                                   float* __restrict__ out)
{
    __shared__ float sK[STRIP * E_];
    __shared__ float sV[STRIP * E_];

    int t0 = blockIdx.x * TT;
    int bj = blockIdx.y;
    int base_row = bj * T_;
    int tid = threadIdx.x;

    for (int i = tid; i < STRIP * (E_ / 4); i += 256) {
        int r  = i >> 6;
        int c4 = i & 63;
        int tt = t0 - W_ + r;
        tt = min(max(tt, 0), T_ - 1);
        size_t g = (size_t)(base_row + tt) * E_ + c4 * 4;
        *reinterpret_cast<float4*>(&sK[r * E_ + c4 * 4]) =
            *reinterpret_cast<const float4*>(&g_k[g]);
        *reinterpret_cast<float4*>(&sV[r * E_ + c4 * 4]) =
            *reinterpret_cast<const float4*>(&g_v[g]);
    }
    __syncthreads();

    int warp = tid >> 5, lane = tid & 31;
    float inv_scale = 1.0f / (16.0f * fmaxf(tau[0], 0.001f));

    #pragma unroll
    for (int s = 0; s < 2; s++) {
        int t = t0 + warp * 2 + s;
        if (t >= T_) continue;
        int lrow = t - t0;

        size_t qoff = (size_t)(base_row + t) * E_ + lane * 8;
        float4 q0 = *reinterpret_cast<const float4*>(&g_q[qoff]);
        float4 q1 = *reinterpret_cast<const float4*>(&g_q[qoff + 4]);

        float dot[KW_];
        #pragma unroll
        for (int w = 0; w < KW_; w++) {
            const float* kr = &sK[(lrow + w) * E_ + lane * 8];
            float4 k0 = *reinterpret_cast<const float4*>(kr);
            float4 k1 = *reinterpret_cast<const float4*>(kr + 4);
            float d = q0.x * k0.x + q0.y * k0.y + q0.z * k0.z + q0.w * k0.w
                    + q1.x * k1.x + q1.y * k1.y + q1.z * k1.z + q1.w * k1.w;
            #pragma unroll
            for (int o = 16; o > 0; o >>= 1) d += __shfl_xor_sync(0xffffffffu, d, o);
            dot[w] = d;
        }

        float m = -1e30f, logit[KW_];
        #pragma unroll
        for (int w = 0; w < KW_; w++) {
            int tt = t + w - W_;
            bool valid = (tt >= 0) && (tt < T_);
            logit[w] = valid ? dot[w] * inv_scale : -1e30f;
            m = fmaxf(m, logit[w]);
        }
        float e[KW_], esum = 0.f;
        #pragma unroll
        for (int w = 0; w < KW_; w++) {
            int tt = t + w - W_;
            bool valid = (tt >= 0) && (tt < T_);
            e[w] = valid ? __expf(logit[w] - m) : 0.f;
            esum += e[w];
        }
        float inv_esum = 1.0f / esum;

        float agg[8] = {0.f, 0.f, 0.f, 0.f, 0.f, 0.f, 0.f, 0.f};
        #pragma unroll
        for (int w = 0; w < KW_; w++) {
            int tt = t + w - W_;
            if (tt >= 0 && tt < T_) {
                float wt = e[w] * inv_esum;
                const float* vr = &sV[(lrow + w) * E_ + lane * 8];
                float4 v0 = *reinterpret_cast<const float4*>(vr);
                float4 v1 = *reinterpret_cast<const float4*>(vr + 4);
                agg[0] = fmaf(wt, v0.x, agg[0]); agg[1] = fmaf(wt, v0.y, agg[1]);
                agg[2] = fmaf(wt, v0.z, agg[2]); agg[3] = fmaf(wt, v0.w, agg[3]);
                agg[4] = fmaf(wt, v1.x, agg[4]); agg[5] = fmaf(wt, v1.y, agg[5]);
                agg[6] = fmaf(wt, v1.z, agg[6]); agg[7] = fmaf(wt, v1.w, agg[7]);
            }
        }

        float ss = 0.f;
        #pragma unroll
        for (int i = 0; i < 8; i++) ss = fmaf(agg[i], agg[i], ss);
        #pragma unroll
        for (int o = 16; o > 0; o >>= 1) ss += __shfl_xor_sync(0xffffffffu, ss, o);

        float n = fmaxf(sqrtf(ss), 1e-7f);
        float coef = sinhf(n) / n;

        int b = bj / J_;
        int j = bj - b * J_;
        size_t obase = ((size_t)(b * T_ + t) * J_ + j) * D_;
        #pragma unroll
        for (int i = 0; i < 8; i++)
            out[obase + 1 + lane * 8 + i] = coef * agg[i];
        if (lane == 0) out[obase] = coshf(sqrtf(ss));
    }
}

// ---------------------------------------------------------------------------
extern "C" void kernel_launch(void* const* d_in, const int* in_sizes, int n_in,
                              void* d_out, int out_size)
{
    const float* x    = (const float*)d_in[0];
    // d_in[1] = vel_seq (unused by reference)
    const float* tau  = (const float*)d_in[2];
    const float* Wq   = (const float*)d_in[3];
    const float* bq   = (const float*)d_in[4];
    const float* Wk   = (const float*)d_in[5];
    const float* bk   = (const float*)d_in[6];
    const float* Wv   = (const float*)d_in[7];
    const float* bv   = (const float*)d_in[8];
    float* out = (float*)d_out;

    wsplit_kernel<<<E_ * E_ / 256, 256>>>(Wq, Wk, Wv);
    logmap_kernel<<<(ROWS + 7) / 8, 256>>>(x);

    cudaFuncSetAttribute(qkv_gemm_tc,
                         cudaFuncAttributeMaxDynamicSharedMemorySize, GEMM_SMEM);
    dim3 g2(6, MTILES);
    qkv_gemm_tc<<<g2, 256, GEMM_SMEM>>>(bq, bk, bv);

    dim3 g3((T_ + TT - 1) / TT, B_ * J_);
    attn_kernel<<<g3, 256>>>(tau, out);
}